// round 14
// baseline (speedup 1.0000x reference)
#include <cuda_runtime.h>
#include <math.h>

#define BSZ 4096
#define CSZ 16000
#define C4  4000
#define NM1 15999.0f
#define LOG2E 1.4426950408889634f
#define BIG125 4.2535295865117308e37f   // 2^125, exact power of two

// ---------------- scratch (device globals) ----------------------------------
__device__ float4   g_stats4[BSZ];         // {cs=-log2(Zs), ms, ct=-log2(Zt), mt}
__device__ int      g_cnt[2][BSZ][10];
__device__ int      g_amax[2][BSZ];
__device__ float    g_s1[CSZ], g_s2[CSZ], g_t1[CSZ], g_t2[CSZ], g_st[CSZ];
__device__ double   g_acc[3];              // intra, spearman, equal
__device__ unsigned g_tickets;

static __device__ __forceinline__ float ex2f(float x) {
    float y;
    asm("ex2.approx.f32 %0, %1;" : "=f"(y) : "f"(x));
    return y;
}

// EXACT strict-less indicator: 1.0f iff x < u, where uB = u * 2^125 (exact).
// FFMA-imm (rt_SMSP=1): (u-x)*2^125 sign-exact, sat clamps to {0,1}, x==u -> 0.
static __device__ __forceinline__ float satlt(float x, float uB) {
    float t;
    asm("fma.rn.sat.f32 %0, %1, 0fFE000000, %2;" : "=f"(t) : "f"(x), "f"(uB));
    return t;
}
// acc += 2*t as FFMA-imm (multiplier 2.0 immediate, cannot fold to FADD)
static __device__ __forceinline__ void acc2(float& acc, float t) {
    asm("fma.rn.f32 %0, %1, 0f40000000, %0;" : "+f"(acc) : "f"(t));
}

// ---------------- kernel 1: row pass (max, sum-exp, 10 rank counts) ----------
__global__ void __launch_bounds__(256) k_rowstats(const float* __restrict__ zs,
                                                  const float* __restrict__ zt) {
    const int b = blockIdx.x;
    const int t = blockIdx.y;

    // ---- folded init ----
    if (threadIdx.x == 10) g_amax[t][b] = 0x7FFFFFFF;
    if (threadIdx.x < 10) {
        int i = (b * 2 + t) * 10 + threadIdx.x;
        if (i < CSZ) {
            g_s1[i] = 0.f; g_s2[i] = 0.f; g_t1[i] = 0.f; g_t2[i] = 0.f; g_st[i] = 0.f;
        }
    }
    if (b == 0 && t == 0) {
        if (threadIdx.x == 11) { g_acc[0] = 0.0; g_acc[1] = 0.0; g_acc[2] = 0.0; }
        if (threadIdx.x == 12) g_tickets = 0u;
    }

    const float* row = (t == 0 ? zs : zt) + (size_t)b * CSZ;
    const float4* row4 = (const float4*)row;

    float uB[10];
#pragma unroll
    for (int j = 0; j < 10; j++) uB[j] = row[j] * BIG125;   // exact (pow2 scale)

    float mx = -1e30f;
    float sm0 = 0.f, sm1 = 0.f, sm2 = 0.f, sm3 = 0.f;
    float fc[10];
#pragma unroll
    for (int j = 0; j < 10; j++) fc[j] = 0.f;

#pragma unroll 8
    for (int i = threadIdx.x; i < C4; i += 256) {
        float4 v = row4[i];
        sm0 += ex2f(v.x * LOG2E);
        sm1 += ex2f(v.y * LOG2E);
        sm2 += ex2f(v.z * LOG2E);
        sm3 += ex2f(v.w * LOG2E);
        mx = fmaxf(mx, fmaxf(fmaxf(v.x, v.y), fmaxf(v.z, v.w)));
#pragma unroll
        for (int j = 0; j < 10; j++) {
            acc2(fc[j], satlt(v.x, uB[j]));
            acc2(fc[j], satlt(v.y, uB[j]));
            acc2(fc[j], satlt(v.z, uB[j]));
            acc2(fc[j], satlt(v.w, uB[j]));
        }
    }
    float sm = (sm0 + sm1) + (sm2 + sm3);

    const unsigned FULL = 0xffffffffu;
#pragma unroll
    for (int o = 16; o; o >>= 1) {
        mx = fmaxf(mx, __shfl_xor_sync(FULL, mx, o));
        sm += __shfl_xor_sync(FULL, sm, o);
#pragma unroll
        for (int j = 0; j < 10; j++) fc[j] += __shfl_xor_sync(FULL, fc[j], o);
    }

    __shared__ float smx[8], ssm[8], sfc[8][10];
    int w = threadIdx.x >> 5, lane = threadIdx.x & 31;
    if (lane == 0) {
        smx[w] = mx; ssm[w] = sm;
#pragma unroll
        for (int j = 0; j < 10; j++) sfc[w][j] = fc[j];
    }
    __syncthreads();
    if (threadIdx.x == 0) {
#pragma unroll
        for (int ww = 1; ww < 8; ww++) {
            mx = fmaxf(mx, smx[ww]);
            sm += ssm[ww];
#pragma unroll
            for (int j = 0; j < 10; j++) fc[j] += sfc[ww][j];
        }
        // pack per-row constants: t=0 writes {cs, ms}, t=1 writes {ct, mt}
        ((float2*)g_stats4)[b * 2 + t] = make_float2(-log2f(sm), mx);
#pragma unroll
        for (int j = 0; j < 10; j++) g_cnt[t][b][j] = __float2int_rn(fc[j] * 0.5f);
    }
}

// ---------------- kernel 2: column pass (intra stats + argmax) ---------------
// grid (16, 128): 1024 cols per x-block, 32 rows per y-block. Row-block order
// reversed so the first blocks hit rows rowstats left in L2.
__global__ void __launch_bounds__(256) k_colstats(const float* __restrict__ zs,
                                                  const float* __restrict__ zt) {
    const int c = blockIdx.x * 1024 + threadIdx.x * 4;
    if (c >= CSZ) return;
    const int r0 = (127 - blockIdx.y) * 32;

    float a1[4] = {0, 0, 0, 0}, a2[4] = {0, 0, 0, 0};
    float b1[4] = {0, 0, 0, 0}, b2[4] = {0, 0, 0, 0};
    float ab[4] = {0, 0, 0, 0};

#pragma unroll 8
    for (int rr = 0; rr < 32; rr++) {
        const int r = r0 + rr;
        const float4 st = g_stats4[r];                 // {cs, ms, ct, mt}, one LDG.128
        const float4 xs = __ldcs((const float4*)(zs + (size_t)r * CSZ + c));
        const float4 xt = __ldcs((const float4*)(zt + (size_t)r * CSZ + c));
#pragma unroll
        for (int k = 0; k < 4; k++) {
            float xsk = (k == 0 ? xs.x : k == 1 ? xs.y : k == 2 ? xs.z : xs.w);
            float xtk = (k == 0 ? xt.x : k == 1 ? xt.y : k == 2 ? xt.z : xt.w);
            float ys = ex2f(fmaf(xsk, LOG2E, st.x));
            float yt = ex2f(fmaf(xtk, LOG2E, st.z));
            a1[k] += ys; a2[k] = fmaf(ys, ys, a2[k]);
            b1[k] += yt; b2[k] = fmaf(yt, yt, b2[k]);
            ab[k] = fmaf(ys, yt, ab[k]);
            if (xsk == st.y) atomicMin(&g_amax[0][r], c + k);
            if (xtk == st.w) atomicMin(&g_amax[1][r], c + k);
        }
    }
#pragma unroll
    for (int k = 0; k < 4; k++) {
        atomicAdd(&g_s1[c + k], a1[k]);
        atomicAdd(&g_s2[c + k], a2[k]);
        atomicAdd(&g_t1[c + k], b1[k]);
        atomicAdd(&g_t2[c + k], b2[k]);
        atomicAdd(&g_st[c + k], ab[k]);
    }
}

// ---------------- kernel 3: fused partial + final reduction ------------------
__global__ void __launch_bounds__(256) k_final(float* __restrict__ out) {
    const int bid = blockIdx.x;
    const int tid = threadIdx.x;
    __shared__ double sh0[256], sh1[256];

    double v0 = 0.0, v1 = 0.0;
    int slot0, slot1 = -1;

    if (bid < 64) {
        slot0 = 0;                                  // intra
        const float invB = 1.f / (float)BSZ;
        int c = bid * 250 + tid;
        if (tid < 250) {
            float s1 = g_s1[c], s2 = g_s2[c], t1 = g_t1[c], t2 = g_t2[c], st = g_st[c];
            float num = st - s1 * t1 * invB;
            float vs = s2 - s1 * s1 * invB;
            float vt = t2 - t1 * t1 * invB;
            float den = sqrtf(fmaxf(vs, 0.f)) * sqrtf(fmaxf(vt, 0.f)) + 1e-8f;
            v0 = (double)(num / den);
        }
    } else {
        slot0 = 1; slot1 = 2;                       // spearman, equal
        const int b = (bid - 64) * 256 + tid;
        const int js = g_amax[0][b], jt = g_amax[1][b];
        v1 = (js == jt) ? 1.0 : 0.0;

        int ms[10], mt[10];
        bool ks[10], kt[10];
        float Ds = 0.f, Qs = 0.f, Dt = 0.f, Qt = 0.f;
#pragma unroll
        for (int i = 0; i < 10; i++) {
            int p = g_cnt[0][b][i];
            ks[i] = (p != js);
            ms[i] = p - (p > js ? 1 : 0);
            float v = (float)(10 - i);
            if (ks[i]) { Ds += v; Qs += v * v; }
            p = g_cnt[1][b][i];
            kt[i] = (p != jt);
            mt[i] = p - (p > jt ? 1 : 0);
            if (kt[i]) { Dt += v; Qt += v * v; }
        }
        float X = 0.f;
#pragma unroll
        for (int i = 0; i < 10; i++) {
#pragma unroll
            for (int k2 = 0; k2 < 10; k2++) {
                if (ks[i] && kt[k2] && (ms[i] == mt[k2]))
                    X += (float)(10 - i) * (float)(10 - k2);
            }
        }
        float num = X - Ds * Dt / NM1;
        float den = sqrtf(fmaxf(Qs - Ds * Ds / NM1, 0.f)) *
                    sqrtf(fmaxf(Qt - Dt * Dt / NM1, 0.f)) + 1e-8f;
        v0 = (double)(num / den);
    }

    sh0[tid] = v0; sh1[tid] = v1;
    __syncthreads();
    for (int s = 128; s; s >>= 1) {
        if (tid < s) { sh0[tid] += sh0[tid + s]; sh1[tid] += sh1[tid + s]; }
        __syncthreads();
    }

    if (tid == 0) {
        atomicAdd(&g_acc[slot0], sh0[0]);
        if (slot1 >= 0) atomicAdd(&g_acc[slot1], sh1[0]);
        __threadfence();
        unsigned ticket = atomicAdd(&g_tickets, 1u);
        if (ticket == 79u) {
            __threadfence();
            double intra = ((volatile double*)g_acc)[0];
            double sp    = ((volatile double*)g_acc)[1];
            double eq    = ((volatile double*)g_acc)[2];
            double inter_loss = 1.0 - (eq / (double)BSZ + sp / (double)BSZ);
            double intra_loss = 1.0 - intra / (double)CSZ;
            out[0] = (float)(inter_loss + intra_loss);
        }
    }
}

// ---------------- launch ------------------------------------------------------
extern "C" void kernel_launch(void* const* d_in, const int* in_sizes, int n_in,
                              void* d_out, int out_size) {
    const float* zs = (const float*)d_in[0];
    const float* zt = (const float*)d_in[1];

    dim3 g1(BSZ, 2);
    k_rowstats<<<g1, 256>>>(zs, zt);

    dim3 g2(16, 128);
    k_colstats<<<g2, 256>>>(zs, zt);

    k_final<<<80, 256>>>((float*)d_out);
}

// round 16
// speedup vs baseline: 1.4062x; 1.4062x over previous
#include <cuda_runtime.h>
#include <math.h>

#define BSZ 4096
#define CSZ 16000
#define C4  4000
#define NM1 15999.0f
#define LOG2E 1.4426950408889634f
#define BIG125 4.2535295865117308e37f   // 2^125, exact power of two

// ---------------- scratch (device globals) ----------------------------------
__device__ float4   g_stats4[BSZ];         // {cs=-log2(Zs), ms, ct=-log2(Zt), mt}
__device__ int      g_cnt[2][BSZ][10];
__device__ int      g_amax[2][BSZ];
__device__ float    g_s1[CSZ], g_s2[CSZ], g_t1[CSZ], g_t2[CSZ], g_st[CSZ];
__device__ double   g_acc[3];              // intra, spearman, equal
__device__ unsigned g_tickets;

static __device__ __forceinline__ float ex2f(float x) {
    float y;
    asm("ex2.approx.f32 %0, %1;" : "=f"(y) : "f"(x));
    return y;
}

// EXACT strict-less indicator: 1.0f iff x < u, where uB = u * 2^125 (exact).
// FFMA-imm (rt_SMSP=1): (u-x)*2^125 sign-exact, sat clamps to {0,1}, x==u -> 0.
static __device__ __forceinline__ float satlt(float x, float uB) {
    float t;
    asm("fma.rn.sat.f32 %0, %1, 0fFE000000, %2;" : "=f"(t) : "f"(x), "f"(uB));
    return t;
}
// acc += 2*t as FFMA-imm (multiplier 2.0 immediate, cannot fold to FADD)
static __device__ __forceinline__ void acc2(float& acc, float t) {
    asm("fma.rn.f32 %0, %1, 0f40000000, %0;" : "+f"(acc) : "f"(t));
}

// ---------------- kernel 1: row pass (max, sum-exp, 10 rank counts) ----------
__global__ void __launch_bounds__(256) k_rowstats(const float* __restrict__ zs,
                                                  const float* __restrict__ zt) {
    const int b = blockIdx.x;
    const int t = blockIdx.y;

    // ---- folded init ----
    if (threadIdx.x == 10) g_amax[t][b] = 0x7FFFFFFF;
    if (threadIdx.x < 10) {
        int i = (b * 2 + t) * 10 + threadIdx.x;
        if (i < CSZ) {
            g_s1[i] = 0.f; g_s2[i] = 0.f; g_t1[i] = 0.f; g_t2[i] = 0.f; g_st[i] = 0.f;
        }
    }
    if (b == 0 && t == 0) {
        if (threadIdx.x == 11) { g_acc[0] = 0.0; g_acc[1] = 0.0; g_acc[2] = 0.0; }
        if (threadIdx.x == 12) g_tickets = 0u;
    }

    const float* row = (t == 0 ? zs : zt) + (size_t)b * CSZ;
    const float4* row4 = (const float4*)row;

    float uB[10];
#pragma unroll
    for (int j = 0; j < 10; j++) uB[j] = row[j] * BIG125;   // exact (pow2 scale)

    float mx = -1e30f;
    float sm0 = 0.f, sm1 = 0.f, sm2 = 0.f, sm3 = 0.f;
    float fc[10];
#pragma unroll
    for (int j = 0; j < 10; j++) fc[j] = 0.f;

#pragma unroll 8
    for (int i = threadIdx.x; i < C4; i += 256) {
        float4 v = row4[i];
        sm0 += ex2f(v.x * LOG2E);
        sm1 += ex2f(v.y * LOG2E);
        sm2 += ex2f(v.z * LOG2E);
        sm3 += ex2f(v.w * LOG2E);
        mx = fmaxf(mx, fmaxf(fmaxf(v.x, v.y), fmaxf(v.z, v.w)));
#pragma unroll
        for (int j = 0; j < 10; j++) {
            acc2(fc[j], satlt(v.x, uB[j]));
            acc2(fc[j], satlt(v.y, uB[j]));
            acc2(fc[j], satlt(v.z, uB[j]));
            acc2(fc[j], satlt(v.w, uB[j]));
        }
    }
    float sm = (sm0 + sm1) + (sm2 + sm3);

    const unsigned FULL = 0xffffffffu;
#pragma unroll
    for (int o = 16; o; o >>= 1) {
        mx = fmaxf(mx, __shfl_xor_sync(FULL, mx, o));
        sm += __shfl_xor_sync(FULL, sm, o);
#pragma unroll
        for (int j = 0; j < 10; j++) fc[j] += __shfl_xor_sync(FULL, fc[j], o);
    }

    __shared__ float smx[8], ssm[8], sfc[8][10];
    int w = threadIdx.x >> 5, lane = threadIdx.x & 31;
    if (lane == 0) {
        smx[w] = mx; ssm[w] = sm;
#pragma unroll
        for (int j = 0; j < 10; j++) sfc[w][j] = fc[j];
    }
    __syncthreads();
    if (threadIdx.x == 0) {
#pragma unroll
        for (int ww = 1; ww < 8; ww++) {
            mx = fmaxf(mx, smx[ww]);
            sm += ssm[ww];
#pragma unroll
            for (int j = 0; j < 10; j++) fc[j] += sfc[ww][j];
        }
        // pack per-row constants: t=0 writes {cs, ms}, t=1 writes {ct, mt}
        ((float2*)g_stats4)[b * 2 + t] = make_float2(-log2f(sm), mx);
#pragma unroll
        for (int j = 0; j < 10; j++) g_cnt[t][b][j] = __float2int_rn(fc[j] * 0.5f);
    }
}

// ---------------- kernel 2: column pass (intra stats + argmax) ---------------
// grid (16, 128): 1024 cols per x-block, 32 rows per y-block. Row-block order
// reversed so the first blocks hit rows rowstats left in L2.
__global__ void __launch_bounds__(256) k_colstats(const float* __restrict__ zs,
                                                  const float* __restrict__ zt) {
    const int c = blockIdx.x * 1024 + threadIdx.x * 4;
    if (c >= CSZ) return;
    const int r0 = (127 - blockIdx.y) * 32;

    float a1[4] = {0, 0, 0, 0}, a2[4] = {0, 0, 0, 0};
    float b1[4] = {0, 0, 0, 0}, b2[4] = {0, 0, 0, 0};
    float ab[4] = {0, 0, 0, 0};

#pragma unroll 8
    for (int rr = 0; rr < 32; rr++) {
        const int r = r0 + rr;
        const float4 st = g_stats4[r];                 // {cs, ms, ct, mt}, one LDG.128
        const float4 xs = __ldcs((const float4*)(zs + (size_t)r * CSZ + c));
        const float4 xt = __ldcs((const float4*)(zt + (size_t)r * CSZ + c));
#pragma unroll
        for (int k = 0; k < 4; k++) {
            float xsk = (k == 0 ? xs.x : k == 1 ? xs.y : k == 2 ? xs.z : xs.w);
            float xtk = (k == 0 ? xt.x : k == 1 ? xt.y : k == 2 ? xt.z : xt.w);
            float ys = ex2f(fmaf(xsk, LOG2E, st.x));
            float yt = ex2f(fmaf(xtk, LOG2E, st.z));
            a1[k] += ys; a2[k] = fmaf(ys, ys, a2[k]);
            b1[k] += yt; b2[k] = fmaf(yt, yt, b2[k]);
            ab[k] = fmaf(ys, yt, ab[k]);
            if (xsk == st.y) atomicMin(&g_amax[0][r], c + k);
            if (xtk == st.w) atomicMin(&g_amax[1][r], c + k);
        }
    }
#pragma unroll
    for (int k = 0; k < 4; k++) {
        atomicAdd(&g_s1[c + k], a1[k]);
        atomicAdd(&g_s2[c + k], a2[k]);
        atomicAdd(&g_t1[c + k], b1[k]);
        atomicAdd(&g_t2[c + k], b2[k]);
        atomicAdd(&g_st[c + k], ab[k]);
    }
}

// ---------------- kernel 3: fused partial + final reduction ------------------
__global__ void __launch_bounds__(256) k_final(float* __restrict__ out) {
    const int bid = blockIdx.x;
    const int tid = threadIdx.x;
    __shared__ double sh0[256], sh1[256];

    double v0 = 0.0, v1 = 0.0;
    int slot0, slot1 = -1;

    if (bid < 64) {
        slot0 = 0;                                  // intra
        const float invB = 1.f / (float)BSZ;
        int c = bid * 250 + tid;
        if (tid < 250) {
            float s1 = g_s1[c], s2 = g_s2[c], t1 = g_t1[c], t2 = g_t2[c], st = g_st[c];
            float num = st - s1 * t1 * invB;
            float vs = s2 - s1 * s1 * invB;
            float vt = t2 - t1 * t1 * invB;
            float den = sqrtf(fmaxf(vs, 0.f)) * sqrtf(fmaxf(vt, 0.f)) + 1e-8f;
            v0 = (double)(num / den);
        }
    } else {
        slot0 = 1; slot1 = 2;                       // spearman, equal
        const int b = (bid - 64) * 256 + tid;
        const int js = g_amax[0][b], jt = g_amax[1][b];
        v1 = (js == jt) ? 1.0 : 0.0;

        int ms[10], mt[10];
        bool ks[10], kt[10];
        float Ds = 0.f, Qs = 0.f, Dt = 0.f, Qt = 0.f;
#pragma unroll
        for (int i = 0; i < 10; i++) {
            int p = g_cnt[0][b][i];
            ks[i] = (p != js);
            ms[i] = p - (p > js ? 1 : 0);
            float v = (float)(10 - i);
            if (ks[i]) { Ds += v; Qs += v * v; }
            p = g_cnt[1][b][i];
            kt[i] = (p != jt);
            mt[i] = p - (p > jt ? 1 : 0);
            if (kt[i]) { Dt += v; Qt += v * v; }
        }
        float X = 0.f;
#pragma unroll
        for (int i = 0; i < 10; i++) {
#pragma unroll
            for (int k2 = 0; k2 < 10; k2++) {
                if (ks[i] && kt[k2] && (ms[i] == mt[k2]))
                    X += (float)(10 - i) * (float)(10 - k2);
            }
        }
        float num = X - Ds * Dt / NM1;
        float den = sqrtf(fmaxf(Qs - Ds * Ds / NM1, 0.f)) *
                    sqrtf(fmaxf(Qt - Dt * Dt / NM1, 0.f)) + 1e-8f;
        v0 = (double)(num / den);
    }

    sh0[tid] = v0; sh1[tid] = v1;
    __syncthreads();
    for (int s = 128; s; s >>= 1) {
        if (tid < s) { sh0[tid] += sh0[tid + s]; sh1[tid] += sh1[tid + s]; }
        __syncthreads();
    }

    if (tid == 0) {
        atomicAdd(&g_acc[slot0], sh0[0]);
        if (slot1 >= 0) atomicAdd(&g_acc[slot1], sh1[0]);
        __threadfence();
        unsigned ticket = atomicAdd(&g_tickets, 1u);
        if (ticket == 79u) {
            __threadfence();
            double intra = ((volatile double*)g_acc)[0];
            double sp    = ((volatile double*)g_acc)[1];
            double eq    = ((volatile double*)g_acc)[2];
            double inter_loss = 1.0 - (eq / (double)BSZ + sp / (double)BSZ);
            double intra_loss = 1.0 - intra / (double)CSZ;
            out[0] = (float)(inter_loss + intra_loss);
        }
    }
}

// ---------------- launch ------------------------------------------------------
extern "C" void kernel_launch(void* const* d_in, const int* in_sizes, int n_in,
                              void* d_out, int out_size) {
    const float* zs = (const float*)d_in[0];
    const float* zt = (const float*)d_in[1];

    dim3 g1(BSZ, 2);
    k_rowstats<<<g1, 256>>>(zs, zt);

    dim3 g2(16, 128);
    k_colstats<<<g2, 256>>>(zs, zt);

    k_final<<<80, 256>>>((float*)d_out);
}